// round 16
// baseline (speedup 1.0000x reference)
#include <cuda_runtime.h>

// Problem constants
#define K_COLORS 512
#define NGRP     (K_COLORS / 4)       // 128 groups of 4 colors
#define HW       65536                // 256*256
#define B        8
#define PPT      2                    // pixels (batch images) per thread
#define NTHREADS 128
#define NBLOCKS  2048                 // 262144 threads = HW * (B/PPT)
#define NPIX     (HW * B)             // 524288
#define NOUT     (NPIX * 3)           // 1572864

// One group = 4 consecutive colors, coefficients pre-paired for f32x2 math:
// a0 = {(-2t0_k,-2t0_k+1),(-2t0_k+2,-2t0_k+3)}, likewise a1/a2/nn.
struct Grp { ulonglong2 a0, a1, a2, nn; };

__constant__ Grp    cG[NGRP];         // palette in const bank
__device__   Grp    gG[NGRP];         // staging, written by prep_kernel
__device__   float4 gC4[K_COLORS];    // AoS (-2t0,-2t1,-2t2,n) for the rescan

__device__ float        g_partials[NBLOCKS];
__device__ unsigned int g_count = 0;

__device__ __forceinline__ unsigned long long bc2(float x) {
    unsigned int u = __float_as_uint(x);
    return ((unsigned long long)u << 32) | u;
}
__device__ __forceinline__ float lo_f(unsigned long long v) {
    return __uint_as_float((unsigned int)v);
}

// ONE fused asm block per (group, pixel): 6x fma.rn.f32x2 + mov.b64 splits +
// 3x min.f32. Chain order matches the reference scalar fmaf chain exactly:
//   d = fma(x, a0, fma(y, a1, fma(z, a2, n)))  per color (per packed half).
__device__ __forceinline__ float group_min4(
    unsigned long long X, unsigned long long Y, unsigned long long Z,
    const Grp& gr)
{
    float m;
    asm("{\n\t"
        ".reg .b64 p, q;\n\t"
        ".reg .f32 a, b, c, d, u, v;\n\t"
        "fma.rn.f32x2 p, %3, %6, %7;\n\t"     // Z*a2.x + nn.x
        "fma.rn.f32x2 p, %2, %5, p;\n\t"      // Y*a1.x + p
        "fma.rn.f32x2 p, %1, %4, p;\n\t"      // X*a0.x + p  -> colors k,k+1
        "fma.rn.f32x2 q, %3, %10, %11;\n\t"   // Z*a2.y + nn.y
        "fma.rn.f32x2 q, %2, %9, q;\n\t"      // Y*a1.y + q
        "fma.rn.f32x2 q, %1, %8, q;\n\t"      // X*a0.y + q  -> colors k+2,k+3
        "mov.b64 {a, b}, p;\n\t"
        "mov.b64 {c, d}, q;\n\t"
        "min.f32 u, a, b;\n\t"
        "min.f32 v, c, d;\n\t"
        "min.f32 %0, u, v;\n\t"
        "}"
        : "=f"(m)
        : "l"(X), "l"(Y), "l"(Z),
          "l"(gr.a0.x), "l"(gr.a1.x), "l"(gr.a2.x), "l"(gr.nn.x),
          "l"(gr.a0.y), "l"(gr.a1.y), "l"(gr.a2.y), "l"(gr.nn.y));
    return m;
}

__global__ void __launch_bounds__(K_COLORS) prep_kernel(
    const float* __restrict__ table)
{
    const int k = threadIdx.x;
    float t0 = table[3 * k + 0];
    float t1 = table[3 * k + 1];
    float t2 = table[3 * k + 2];
    float n  = __fadd_rn(__fadd_rn(__fmul_rn(t0, t0), __fmul_rn(t1, t1)),
                         __fmul_rn(t2, t2));
    float a0 = -2.0f * t0, a1 = -2.0f * t1, a2 = -2.0f * t2;
    const int g4 = k >> 2, lane = k & 3;
    float* base = (float*)&gG[g4];
    base[0 * 4 + lane] = a0;
    base[1 * 4 + lane] = a1;
    base[2 * 4 + lane] = a2;
    base[3 * 4 + lane] = n;
    gC4[k] = make_float4(a0, a1, a2, n);
}

// Fused VQ + straight-through output + loss.
//
// ROUND-16: the untested cell of the (PPT x palette-port) matrix. Calibrated
// model (rounds 9-15): per-SM port cost = warps/SM x vec-loads/warp x rate
// (LDC.128 ~7cyc, broadcast LDS.128 ~4.4cyc, both serialized per-SM), and
// eligibility needs >=10 warps/SMSP. PPT=2 gives 13.8 warps/SMSP (fixes
// eligibility) and the 3:5 const:smem interleave balances the two ports at
// ~37k/~39k cyc per SM — both below the fma-pipe bound, on separate pipes.
// Round 11 (PPT=2, ALL-const) failed only because 28k LDC x 7 = 196k cyc
// saturated the const port; this split removes that.
//
// Exactness: strict '<' commit in ascending group order (earliest group on
// ties); final 4-color rescan recomputes the bit-identical scalar FMA chain
// (f32x2 halves are IEEE-identical to fma.rn.f32); first '==' match is the
// argmin (jnp.argmin first-index semantics). Bit-validated rounds 4/6-15.
__global__ void __launch_bounds__(NTHREADS, 10) vq_kernel(
    const float* __restrict__ z,
    float* __restrict__ out,
    int out_size)
{
    __shared__ Grp   sG[NGRP];         // full palette copy (8 KB)
    __shared__ float sred[NTHREADS];
    __shared__ int   s_last;

    const int tid  = threadIdx.x;

    // Cooperative copy of the palette into smem (512 x 16B).
    {
        const ulonglong2* src = (const ulonglong2*)gG;
        ulonglong2*       dst = (ulonglong2*)sG;
#pragma unroll
        for (int i = tid; i < NGRP * 4; i += NTHREADS) dst[i] = src[i];
    }

    const int g    = blockIdx.x * NTHREADS + tid;   // 0..262143
    const int hw   = g & (HW - 1);
    const int bat0 = (g >> 16) * PPT;               // first batch image

    // Pixel components broadcast into both packed halves (loop-invariant).
    unsigned long long Xb[PPT], Yb[PPT], Zb[PPT];
#pragma unroll
    for (int p = 0; p < PPT; ++p) {
        const int base = (bat0 + p) * 3 * HW + hw;
        Xb[p] = bc2(z[base]);
        Yb[p] = bc2(z[base + HW]);
        Zb[p] = bc2(z[base + 2 * HW]);
    }

    float gbest[PPT];
    int   ggrp[PPT];
#pragma unroll
    for (int p = 0; p < PPT; ++p) { gbest[p] = 3.402823466e38f; ggrp[p] = 0; }

    __syncthreads();   // smem palette ready

    auto process = [&](const Grp gr, const int g4) {
        float m[PPT];
#pragma unroll
        for (int p = 0; p < PPT; ++p)
            m[p] = group_min4(Xb[p], Yb[p], Zb[p], gr);
#pragma unroll
        for (int p = 0; p < PPT; ++p) {
            bool lt  = m[p] < gbest[p];            // earliest group on ties
            gbest[p] = fminf(gbest[p], m[p]);
            ggrp[p]  = lt ? g4 : ggrp[p];
        }
    };

    // Port-balanced interleave per 8 groups: 3 via const bank, 5 via smem
    // (48/80 split balances 7cyc-LDC vs 4.4cyc-LDS serialized costs).
    // Ascending g4 order is preserved exactly.
#pragma unroll 2
    for (int mq = 0; mq < NGRP / 8; ++mq) {
        const int gb = mq << 3;
        process(cG[gb + 0], gb + 0);               // LDC  (const port)
        process(cG[gb + 1], gb + 1);               // LDC
        process(cG[gb + 2], gb + 2);               // LDC
        process(sG[gb + 3], gb + 3);               // LDS  (shared port)
        process(sG[gb + 4], gb + 4);               // LDS
        process(sG[gb + 5], gb + 5);               // LDS
        process(sG[gb + 6], gb + 6);               // LDS
        process(sG[gb + 7], gb + 7);               // LDS
    }

    // Exact index recovery (first '==' match inside the winning 4-color
    // group), fused with the STE epilogue + loss accumulation.
    float lsum = 0.0f;
#pragma unroll
    for (int p = 0; p < PPT; ++p) {
        const int   kb = ggrp[p] << 2;
        const float px = lo_f(Xb[p]);
        const float py = lo_f(Yb[p]);
        const float pz = lo_f(Zb[p]);
        int found = 1023;
#pragma unroll
        for (int i = 0; i < 4; ++i) {
            const float4 cc = __ldg(&gC4[kb + i]);
            float d = fmaf(px, cc.x, fmaf(py, cc.y, fmaf(pz, cc.z, cc.w)));
            int kc = (d == gbest[p]) ? (kb + i) : 1023;
            found  = min(found, kc);
        }
        const float4 cc = __ldg(&gC4[found]);
        float q0 = -0.5f * cc.x;                 // exact recovery of t from -2t
        float q1 = -0.5f * cc.y;
        float q2 = -0.5f * cc.z;
        float d0 = __fsub_rn(q0, px);
        float d1 = __fsub_rn(q1, py);
        float d2 = __fsub_rn(q2, pz);
        const int base = (bat0 + p) * 3 * HW + hw;
        out[base]          = __fadd_rn(px, d0);  // zl + (z_q - zl)
        out[base + HW]     = __fadd_rn(py, d1);
        out[base + 2 * HW] = __fadd_rn(pz, d2);
        lsum = fmaf(d0, d0, lsum);
        lsum = fmaf(d1, d1, lsum);
        lsum = fmaf(d2, d2, lsum);
    }

    // Deterministic block reduction.
    sred[tid] = lsum;
    __syncthreads();
#pragma unroll
    for (int s = NTHREADS / 2; s > 0; s >>= 1) {
        if (tid < s) sred[tid] += sred[tid + s];
        __syncthreads();
    }

    // Last-block-done final reduction (single fused kernel).
    if (tid == 0) {
        g_partials[blockIdx.x] = sred[0];
        __threadfence();
        unsigned int prev = atomicAdd(&g_count, 1u);
        s_last = (prev == NBLOCKS - 1) ? 1 : 0;
    }
    __syncthreads();

    if (s_last) {
        __threadfence();
        volatile float* vp = g_partials;
        float acc = 0.0f;
        for (int i = tid; i < NBLOCKS; i += NTHREADS) acc += vp[i];
        sred[tid] = acc;
        __syncthreads();
#pragma unroll
        for (int s = NTHREADS / 2; s > 0; s >>= 1) {
            if (tid < s) sred[tid] += sred[tid + s];
            __syncthreads();
        }
        if (tid == 0) {
            float m    = sred[0] / (float)NOUT;
            float loss = __fadd_rn(10.0f * m, m);
            for (int i = NOUT; i < out_size; ++i) out[i] = loss;
            g_count = 0;   // reset for the next graph replay
        }
    }
}

extern "C" void kernel_launch(void* const* d_in, const int* in_sizes, int n_in,
                              void* d_out, int out_size)
{
    const float* z     = (const float*)d_in[0];
    const float* table = (const float*)d_in[1];
    float* out         = (float*)d_out;

    prep_kernel<<<1, K_COLORS>>>(table);

    // Stage -> constant bank, device-to-device async (graph-capturable).
    void* gG_addr = nullptr;
    cudaGetSymbolAddress(&gG_addr, gG);
    cudaMemcpyToSymbolAsync(cG, gG_addr, sizeof(gG), 0,
                            cudaMemcpyDeviceToDevice, 0);

    vq_kernel<<<NBLOCKS, NTHREADS>>>(z, out, out_size);
}

// round 17
// speedup vs baseline: 1.5232x; 1.5232x over previous
#include <cuda_runtime.h>

// Problem constants
#define K_COLORS 512
#define NGRP     (K_COLORS / 4)       // 128 groups of 4 colors
#define HW       65536                // 256*256
#define B        8
#define PPT      4                    // pixels (batch images) per thread
#define NTHREADS 128
#define NBLOCKS  1024                 // 131072 threads = HW * (B/PPT)
#define NPIX     (HW * B)             // 524288
#define NOUT     (NPIX * 3)           // 1572864

// One group = 4 consecutive colors, coefficients pre-paired for f32x2 math:
// a0 = {(-2t0_k,-2t0_k+1),(-2t0_k+2,-2t0_k+3)}, likewise a1/a2/nn.
struct Grp { ulonglong2 a0, a1, a2, nn; };

__constant__ Grp    cG[NGRP];         // palette in const bank
__device__   Grp    gG[NGRP];         // staging, written by prep_kernel
__device__   float4 gC4[K_COLORS];    // AoS (-2t0,-2t1,-2t2,n) for the rescan

__device__ float        g_partials[NBLOCKS];
__device__ unsigned int g_count = 0;

// ---- packed f32x2 helpers ----
__device__ __forceinline__ unsigned long long fma2(unsigned long long a,
                                                   unsigned long long b,
                                                   unsigned long long c) {
    unsigned long long d;
    asm("fma.rn.f32x2 %0, %1, %2, %3;" : "=l"(d) : "l"(a), "l"(b), "l"(c));
    return d;
}
__device__ __forceinline__ unsigned long long bc2(float x) {
    unsigned int u = __float_as_uint(x);
    return ((unsigned long long)u << 32) | u;
}
__device__ __forceinline__ float lo_f(unsigned long long v) {
    return __uint_as_float((unsigned int)v);
}
__device__ __forceinline__ float hi_f(unsigned long long v) {
    return __uint_as_float((unsigned int)(v >> 32));
}

__global__ void __launch_bounds__(K_COLORS) prep_kernel(
    const float* __restrict__ table)
{
    const int k = threadIdx.x;
    float t0 = table[3 * k + 0];
    float t1 = table[3 * k + 1];
    float t2 = table[3 * k + 2];
    float n  = __fadd_rn(__fadd_rn(__fmul_rn(t0, t0), __fmul_rn(t1, t1)),
                         __fmul_rn(t2, t2));
    float a0 = -2.0f * t0, a1 = -2.0f * t1, a2 = -2.0f * t2;
    const int g4 = k >> 2, lane = k & 3;
    float* base = (float*)&gG[g4];
    base[0 * 4 + lane] = a0;
    base[1 * 4 + lane] = a1;
    base[2 * 4 + lane] = a2;
    base[3 * 4 + lane] = n;
    gC4[k] = make_float4(a0, a1, a2, n);
}

// Fused VQ + straight-through output + loss.
//
// ROUND-17: SOFTWARE-PIPELINED F/A INTERLEAVE. Diagnosis from rounds 9-16:
// per-SMSP demand is ~21k FFMA2 (fma pipe, rt2 -> 42.5k busy-cycles) plus
// ~23k FMNMX/FSETP/SEL (alu pipe, rt2 -> 46k busy-cycles). Measured runtime
// (~95k cyc) equals the SUM, not the max: the code emitted the work in long
// same-pipe bursts (24 FFMA2 then 24 alu per group), all warps phase-locked
// on identical code, so the two pipes ran sequentially (issue pinned at 50%
// across every occupancy/port config). Fix: one-group software pipeline —
// the FFMA2 distance computation of group g+1 is in flight while the alu
// reduce/commit of group g executes; the two are register-independent, so
// ptxas can alternate F/A issues and run both pipes concurrently.
//
// Exactness: strict '<' commit in ascending group order (earliest group on
// ties); final 4-color rescan recomputes the bit-identical scalar FMA chain
// (f32x2 halves are IEEE-identical to fma.rn.f32); first '==' match is the
// argmin (jnp.argmin first-index semantics). Bit-validated rounds 4/6-16.
__global__ void __launch_bounds__(NTHREADS) vq_kernel(
    const float* __restrict__ z,
    float* __restrict__ out,
    int out_size)
{
    __shared__ Grp   sG[NGRP];         // full palette copy (8 KB)
    __shared__ float sred[NTHREADS];
    __shared__ int   s_last;

    const int tid  = threadIdx.x;

    // Cooperative copy of the palette into smem (512 x 16B).
    {
        const ulonglong2* src = (const ulonglong2*)gG;
        ulonglong2*       dst = (ulonglong2*)sG;
#pragma unroll
        for (int i = tid; i < NGRP * 4; i += NTHREADS) dst[i] = src[i];
    }

    const int g    = blockIdx.x * NTHREADS + tid;   // 0..131071
    const int hw   = g & (HW - 1);
    const int bat0 = (g >> 16) * PPT;               // first batch image

    // Pixel components broadcast into both packed halves (loop-invariant).
    unsigned long long Xb[PPT], Yb[PPT], Zb[PPT];
#pragma unroll
    for (int p = 0; p < PPT; ++p) {
        const int base = (bat0 + p) * 3 * HW + hw;
        Xb[p] = bc2(z[base]);
        Yb[p] = bc2(z[base + HW]);
        Zb[p] = bc2(z[base + 2 * HW]);
    }

    float gbest[PPT];
    int   ggrp[PPT];
#pragma unroll
    for (int p = 0; p < PPT; ++p) { gbest[p] = 3.402823466e38f; ggrp[p] = 0; }

    __syncthreads();   // smem palette ready

    // F-stage: 6 FFMA2 per pixel (2 independent 3-deep chains). Chain order
    // matches the reference scalar fmaf chain exactly:
    //   d = fma(x, a0, fma(y, a1, fma(z, a2, n)))  per packed color pair.
    auto compute_group = [&](const Grp gr,
                             unsigned long long* d01, unsigned long long* d23) {
#pragma unroll
        for (int p = 0; p < PPT; ++p) {
            d01[p] = fma2(Xb[p], gr.a0.x,
                          fma2(Yb[p], gr.a1.x, fma2(Zb[p], gr.a2.x, gr.nn.x)));
            d23[p] = fma2(Xb[p], gr.a0.y,
                          fma2(Yb[p], gr.a1.y, fma2(Zb[p], gr.a2.y, gr.nn.y)));
        }
    };
    // A-stage: min tree + strict-'<' commit (earliest group on exact ties).
    auto commit_group = [&](const unsigned long long* d01,
                            const unsigned long long* d23, const int g4) {
#pragma unroll
        for (int p = 0; p < PPT; ++p) {
            float m = fminf(fminf(lo_f(d01[p]), hi_f(d01[p])),
                            fminf(lo_f(d23[p]), hi_f(d23[p])));
            bool lt  = m < gbest[p];
            gbest[p] = fminf(gbest[p], m);
            ggrp[p]  = lt ? g4 : ggrp[p];
        }
    };
    // Port interleave (1:3 const:smem, identical bits in both copies).
    auto load_grp = [&](const int g4) -> Grp {
        return ((g4 & 3) == 0) ? cG[g4] : sG[g4];
    };

    // One-group software pipeline with ping-pong registers: while group g's
    // alu stage runs, group g+1's fma stage is independent and in flight.
    unsigned long long A01[PPT], A23[PPT], B01[PPT], B23[PPT];
    compute_group(load_grp(0), A01, A23);
#pragma unroll 2
    for (int g4 = 0; g4 < NGRP; g4 += 2) {
        compute_group(load_grp(g4 + 1), B01, B23);   // F for g4+1
        commit_group(A01, A23, g4);                  // A for g4
        if (g4 + 2 < NGRP)
            compute_group(load_grp(g4 + 2), A01, A23); // F for g4+2
        commit_group(B01, B23, g4 + 1);              // A for g4+1
    }

    // Exact index recovery (first '==' match inside the winning 4-color
    // group), fused with the STE epilogue + loss accumulation.
    float lsum = 0.0f;
#pragma unroll
    for (int p = 0; p < PPT; ++p) {
        const int   kb = ggrp[p] << 2;
        const float px = lo_f(Xb[p]);
        const float py = lo_f(Yb[p]);
        const float pz = lo_f(Zb[p]);
        int found = 1023;
#pragma unroll
        for (int i = 0; i < 4; ++i) {
            const float4 cc = __ldg(&gC4[kb + i]);
            float d = fmaf(px, cc.x, fmaf(py, cc.y, fmaf(pz, cc.z, cc.w)));
            int kc = (d == gbest[p]) ? (kb + i) : 1023;
            found  = min(found, kc);
        }
        const float4 cc = __ldg(&gC4[found]);
        float q0 = -0.5f * cc.x;                 // exact recovery of t from -2t
        float q1 = -0.5f * cc.y;
        float q2 = -0.5f * cc.z;
        float d0 = __fsub_rn(q0, px);
        float d1 = __fsub_rn(q1, py);
        float d2 = __fsub_rn(q2, pz);
        const int base = (bat0 + p) * 3 * HW + hw;
        out[base]          = __fadd_rn(px, d0);  // zl + (z_q - zl)
        out[base + HW]     = __fadd_rn(py, d1);
        out[base + 2 * HW] = __fadd_rn(pz, d2);
        lsum = fmaf(d0, d0, lsum);
        lsum = fmaf(d1, d1, lsum);
        lsum = fmaf(d2, d2, lsum);
    }

    // Deterministic block reduction.
    sred[tid] = lsum;
    __syncthreads();
#pragma unroll
    for (int s = NTHREADS / 2; s > 0; s >>= 1) {
        if (tid < s) sred[tid] += sred[tid + s];
        __syncthreads();
    }

    // Last-block-done final reduction (single fused kernel).
    if (tid == 0) {
        g_partials[blockIdx.x] = sred[0];
        __threadfence();
        unsigned int prev = atomicAdd(&g_count, 1u);
        s_last = (prev == NBLOCKS - 1) ? 1 : 0;
    }
    __syncthreads();

    if (s_last) {
        __threadfence();
        volatile float* vp = g_partials;
        float acc = 0.0f;
        for (int i = tid; i < NBLOCKS; i += NTHREADS) acc += vp[i];
        sred[tid] = acc;
        __syncthreads();
#pragma unroll
        for (int s = NTHREADS / 2; s > 0; s >>= 1) {
            if (tid < s) sred[tid] += sred[tid + s];
            __syncthreads();
        }
        if (tid == 0) {
            float m    = sred[0] / (float)NOUT;
            float loss = __fadd_rn(10.0f * m, m);
            for (int i = NOUT; i < out_size; ++i) out[i] = loss;
            g_count = 0;   // reset for the next graph replay
        }
    }
}

extern "C" void kernel_launch(void* const* d_in, const int* in_sizes, int n_in,
                              void* d_out, int out_size)
{
    const float* z     = (const float*)d_in[0];
    const float* table = (const float*)d_in[1];
    float* out         = (float*)d_out;

    prep_kernel<<<1, K_COLORS>>>(table);

    // Stage -> constant bank, device-to-device async (graph-capturable).
    void* gG_addr = nullptr;
    cudaGetSymbolAddress(&gG_addr, gG);
    cudaMemcpyToSymbolAsync(cG, gG_addr, sizeof(gG), 0,
                            cudaMemcpyDeviceToDevice, 0);

    vq_kernel<<<NBLOCKS, NTHREADS>>>(z, out, out_size);
}